// round 6
// baseline (speedup 1.0000x reference)
#include <cuda_runtime.h>

// Problem constants
#define NB    8
#define NDIM  512
#define ND2   1024
#define NT    2048
#define NTOUT 2046   // output columns j = 1 .. T-2

// Input element counts (for size-based, order-robust input mapping)
#define SZ_E   (NB * ND2 * NT)   // 16,777,216
#define SZ_WKQ (ND2 * ND2)       //  1,048,576
#define SZ_WPV (NDIM * ND2)      //    524,288

#define OUT_CPLX (2 * NB * NDIM * NTOUT)  // 16,760,832 floats (interleaved complex)
#define OUT_REAL (NB * NDIM * NTOUT)      //  8,380,416 floats (real part only)

// ---------------------------------------------------------------------------
// Scratch (allocation-free rule: __device__ globals). Zero-initialized .bss.
// g_S lower triangle (i > j) is NEVER written -> stays 0 forever, making the
// final stage's unmasked dot products correct and replay-deterministic.
// ---------------------------------------------------------------------------
__device__ float g_Q_re[(size_t)NB * ND2 * NT];
__device__ float g_Q_im[(size_t)NB * ND2 * NT];
__device__ float g_P_re[(size_t)NB * NDIM * NT];
__device__ float g_P_im[(size_t)NB * NDIM * NT];
__device__ float g_S_re[(size_t)NB * NT * NT];
__device__ float g_S_im[(size_t)NB * NT * NT];

// ---------------------------------------------------------------------------
// One complex SGEMM kernel, specialized by STAGE:
//   STAGE 0:  Q = WKQ @ E          A=[M,K] row-major (M=D2),  B=E,   C=g_Q
//   STAGE 1:  P = WPV @ E          A=[M,K] row-major (M=DIM), B=E,   C=g_P
//   STAGE 2:  S = E^H @ Q (i<=j)   A=E stored [K,M] (conj),   B=g_Q, C=g_S
//   STAGE 3:  out = (1/j) P @ S    A=g_P row-major,           B=g_S, C=out
// Tiling: 128x128x8, 256 threads, 8x8 complex per thread (2x2 quads of 4x4).
// omode: 0 = interleaved complex, 1 = real-only. ocap = float capacity of out.
// ---------------------------------------------------------------------------
constexpr int BM = 128, BN = 128, BK = 8;

template <int STAGE>
__global__ __launch_bounds__(256, 1)
void cgemm_kernel(const float* __restrict__ Are, const float* __restrict__ Aim,
                  const float* __restrict__ Bre, const float* __restrict__ Bim,
                  float* __restrict__ outP, int omode, long long ocap)
{
    constexpr int  LDA    = (STAGE <= 1) ? ND2 : NT;   // stage2: E is [K][M], ld=NT
    constexpr int  LDB    = NT;
    constexpr int  K_TOT  = (STAGE == 3) ? NT : ND2;
    constexpr bool ATRANS = (STAGE == 2);              // A stored [K, M]
    constexpr bool CONJA  = (STAGE == 2);

    const int bz = blockIdx.z;
    const int n0 = blockIdx.x * BN;
    const int m0 = blockIdx.y * BM;

    if (STAGE == 2 && m0 > n0) return;  // tile entirely below diagonal: skip

    const float *are, *aim, *bre, *bim;
    if (STAGE == 0 || STAGE == 1) {            // A = weights (shared), B = E (batched)
        are = Are;  aim = Aim;
        bre = Bre + (size_t)bz * ND2 * NT;
        bim = Bim + (size_t)bz * ND2 * NT;
    } else if (STAGE == 2) {                   // A = E (batched), B = Q (batched)
        are = Are + (size_t)bz * ND2 * NT;
        aim = Aim + (size_t)bz * ND2 * NT;
        bre = g_Q_re + (size_t)bz * ND2 * NT;
        bim = g_Q_im + (size_t)bz * ND2 * NT;
    } else {                                   // A = P, B = S
        are = g_P_re + (size_t)bz * NDIM * NT;
        aim = g_P_im + (size_t)bz * NDIM * NT;
        bre = g_S_re + (size_t)bz * NT * NT;
        bim = g_S_im + (size_t)bz * NT * NT;
    }

    int kEnd = K_TOT;
    if (STAGE == 3) { int ke = n0 + BN; kEnd = ke < K_TOT ? ke : K_TOT; }  // i <= j

    __shared__ float As[2][BK][BM];   // [re/im][k][m]
    __shared__ float Bs[2][BK][BN];   // [re/im][k][n]

    float acc_re[2][2][4][4] = {};
    float acc_im[2][2][4][4] = {};

    const int tid = threadIdx.x;
    const int tx  = tid & 15;
    const int ty  = tid >> 4;

    for (int k0 = 0; k0 < kEnd; k0 += BK) {
        // ---- load A tile ----
        if (ATRANS) {
            const int ak = tid >> 5;            // 0..7
            const int am = (tid & 31) << 2;     // 0..124
            *(float4*)&As[0][ak][am] = *(const float4*)(are + (size_t)(k0 + ak) * LDA + (m0 + am));
            *(float4*)&As[1][ak][am] = *(const float4*)(aim + (size_t)(k0 + ak) * LDA + (m0 + am));
        } else {
            const int arow = tid >> 1;          // 0..127
            const int ak   = (tid & 1) << 2;    // 0 or 4
            const float4 vr = *(const float4*)(are + (size_t)(m0 + arow) * LDA + (k0 + ak));
            const float4 vi = *(const float4*)(aim + (size_t)(m0 + arow) * LDA + (k0 + ak));
            As[0][ak + 0][arow] = vr.x; As[0][ak + 1][arow] = vr.y;
            As[0][ak + 2][arow] = vr.z; As[0][ak + 3][arow] = vr.w;
            As[1][ak + 0][arow] = vi.x; As[1][ak + 1][arow] = vi.y;
            As[1][ak + 2][arow] = vi.z; As[1][ak + 3][arow] = vi.w;
        }
        // ---- load B tile ([K, N] row-major, N contiguous) ----
        {
            const int bk = tid >> 5;
            const int bn = (tid & 31) << 2;
            *(float4*)&Bs[0][bk][bn] = *(const float4*)(bre + (size_t)(k0 + bk) * LDB + (n0 + bn));
            *(float4*)&Bs[1][bk][bn] = *(const float4*)(bim + (size_t)(k0 + bk) * LDB + (n0 + bn));
        }
        __syncthreads();

        #pragma unroll
        for (int kk = 0; kk < BK; kk++) {
            float ar[2][4], ai[2][4], br[2][4], bi[2][4];
            *(float4*)ar[0] = *(const float4*)&As[0][kk][(ty << 2)];
            *(float4*)ar[1] = *(const float4*)&As[0][kk][64 + (ty << 2)];
            *(float4*)ai[0] = *(const float4*)&As[1][kk][(ty << 2)];
            *(float4*)ai[1] = *(const float4*)&As[1][kk][64 + (ty << 2)];
            *(float4*)br[0] = *(const float4*)&Bs[0][kk][(tx << 2)];
            *(float4*)br[1] = *(const float4*)&Bs[0][kk][64 + (tx << 2)];
            *(float4*)bi[0] = *(const float4*)&Bs[1][kk][(tx << 2)];
            *(float4*)bi[1] = *(const float4*)&Bs[1][kk][64 + (tx << 2)];

            #pragma unroll
            for (int mi = 0; mi < 2; mi++)
              #pragma unroll
              for (int ii = 0; ii < 4; ii++) {
                const float xr = ar[mi][ii], xi = ai[mi][ii];
                #pragma unroll
                for (int ni = 0; ni < 2; ni++)
                  #pragma unroll
                  for (int jj = 0; jj < 4; jj++) {
                    const float yr = br[ni][jj], yi = bi[ni][jj];
                    if (CONJA) {
                        acc_re[mi][ni][ii][jj] += xr * yr + xi * yi;
                        acc_im[mi][ni][ii][jj] += xr * yi - xi * yr;
                    } else {
                        acc_re[mi][ni][ii][jj] += xr * yr - xi * yi;
                        acc_im[mi][ni][ii][jj] += xr * yi + xi * yr;
                    }
                  }
              }
        }
        __syncthreads();
    }

    // ---- epilogue ----
    float *cre = nullptr, *cim = nullptr;
    if (STAGE == 0) { cre = g_Q_re + (size_t)bz * ND2 * NT;  cim = g_Q_im + (size_t)bz * ND2 * NT; }
    if (STAGE == 1) { cre = g_P_re + (size_t)bz * NDIM * NT; cim = g_P_im + (size_t)bz * NDIM * NT; }
    if (STAGE == 2) { cre = g_S_re + (size_t)bz * NT * NT;   cim = g_S_im + (size_t)bz * NT * NT; }

    #pragma unroll
    for (int mi = 0; mi < 2; mi++)
      #pragma unroll
      for (int ii = 0; ii < 4; ii++) {
        const int row = m0 + mi * 64 + (ty << 2) + ii;
        #pragma unroll
        for (int ni = 0; ni < 2; ni++)
          #pragma unroll
          for (int jj = 0; jj < 4; jj++) {
            const int col = n0 + ni * 64 + (tx << 2) + jj;
            float vr = acc_re[mi][ni][ii][jj];
            float vi = acc_im[mi][ni][ii][jj];
            if (STAGE == 3) {
                // col == j; output keeps j = 1 .. T-2 at index j-1, scaled 1/j
                if (col >= 1 && col <= NTOUT) {
                    const float s = 1.0f / (float)col;
                    const long long o = ((long long)bz * NDIM + row) * NTOUT + (col - 1);
                    if (omode == 0) {
                        // interleaved complex64 layout, bounds-guarded
                        if (2 * o + 1 < ocap) {
                            outP[2 * o]     = vr * s;
                            outP[2 * o + 1] = vi * s;
                        }
                    } else {
                        // real part only
                        if (o < ocap) outP[o] = vr * s;
                    }
                }
            } else {
                if (STAGE == 2 && row > col) { vr = 0.0f; vi = 0.0f; }  // causal mask
                cre[(size_t)row * NT + col] = vr;
                cim[(size_t)row * NT + col] = vi;
            }
          }
      }
}

// ---------------------------------------------------------------------------
// Launch: robust input mapping + out-layout selection, then 4 dependent GEMM
// stages on the capture stream (stream-ordered, graph-capturable).
// ---------------------------------------------------------------------------
extern "C" void kernel_launch(void* const* d_in, const int* in_sizes, int n_in,
                              void* d_out, int out_size)
{
    // Map inputs by size; accept element counts or byte counts.
    const float* Eptr[2]   = {nullptr, nullptr};
    const float* WKQptr[2] = {nullptr, nullptr};
    const float* WPVptr[2] = {nullptr, nullptr};
    int ne = 0, nk = 0, np = 0;
    for (int i = 0; i < n_in; i++) {
        const float* p = (const float*)d_in[i];
        const long long s = in_sizes[i];
        if (s == SZ_E || s == 4LL * SZ_E)             { if (ne < 2) Eptr[ne++]   = p; }
        else if (s == SZ_WKQ || s == 4LL * SZ_WKQ)    { if (nk < 2) WKQptr[nk++] = p; }
        else if (s == SZ_WPV || s == 4LL * SZ_WPV)    { if (np < 2) WPVptr[np++] = p; }
    }
    if (ne != 2 || nk != 2 || np != 2) {
        // Fallback: setup_inputs() dict order.
        Eptr[0]   = (const float*)d_in[0]; Eptr[1]   = (const float*)d_in[1];
        WKQptr[0] = (const float*)d_in[2]; WKQptr[1] = (const float*)d_in[3];
        WPVptr[0] = (const float*)d_in[4]; WPVptr[1] = (const float*)d_in[5];
    }
    const float* E_re   = Eptr[0];   const float* E_im   = Eptr[1];
    const float* WKQ_re = WKQptr[0]; const float* WKQ_im = WKQptr[1];
    const float* WPV_re = WPVptr[0]; const float* WPV_im = WPVptr[1];
    float* out = (float*)d_out;

    // Output layout from out_size (element count of the output dtype).
    //   == OUT_CPLX : float32 interleaved complex (complex64 viewed as 2 floats)
    //   == OUT_REAL : ambiguous — assume float32 real-part-only (guarded writes
    //                 can't overflow even if it is actually complex64 elements)
    //   otherwise   : guarded interleaved, clamped to out_size floats
    int omode;
    long long ocap;
    if (out_size >= OUT_CPLX)      { omode = 0; ocap = out_size; }
    else if (out_size == OUT_REAL) { omode = 1; ocap = out_size; }
    else                           { omode = 0; ocap = out_size; }

    const dim3 blk(256);

    // Stage 0: Q = WKQ @ E            [B, D2, T]
    cgemm_kernel<0><<<dim3(NT / BN, ND2 / BM, NB), blk>>>(WKQ_re, WKQ_im, E_re, E_im, nullptr, 0, 0);
    // Stage 1: P = WPV @ E            [B, DIM, T]
    cgemm_kernel<1><<<dim3(NT / BN, NDIM / BM, NB), blk>>>(WPV_re, WPV_im, E_re, E_im, nullptr, 0, 0);
    // Stage 2: S = E^H @ Q, causal    [B, T, T] (upper triangle; rest stays 0)
    cgemm_kernel<2><<<dim3(NT / BN, NT / BM, NB), blk>>>(E_re, E_im, nullptr, nullptr, nullptr, 0, 0);
    // Stage 3: out = (1/j) * P @ S    [B, DIM, T-2]
    cgemm_kernel<3><<<dim3(NT / BN, NDIM / BM, NB), blk>>>(nullptr, nullptr, nullptr, nullptr, out, omode, ocap);
}

// round 16
// speedup vs baseline: 2.2730x; 2.2730x over previous
#include <cuda_runtime.h>
#include <cstdint>

// Problem constants
#define NB    8
#define NDIM  512
#define ND2   1024
#define NT    2048
#define NTOUT 2046   // output columns j = 1 .. T-2

#define SZ_E   (NB * ND2 * NT)
#define SZ_WKQ (ND2 * ND2)
#define SZ_WPV (NDIM * ND2)
#define OUT_CPLX (2 * NB * NDIM * NTOUT)
#define OUT_REAL (NB * NDIM * NTOUT)

// fp32 scratch (.bss zero-init). g_S lower triangle never written -> stays 0.
__device__ float g_Q_re[(size_t)NB * ND2 * NT];
__device__ float g_Q_im[(size_t)NB * ND2 * NT];
__device__ float g_P_re[(size_t)NB * NDIM * NT];
__device__ float g_P_im[(size_t)NB * NDIM * NT];
__device__ float g_S_re[(size_t)NB * NT * NT];
__device__ float g_S_im[(size_t)NB * NT * NT];

// Packed f32x2 helpers (Blackwell FFMA2 via PTX; base-family op, not 'a'-gated)
#define PACK2(d, s)  asm("mov.b64 %0, {%1,%1};" : "=l"(d) : "r"(__float_as_uint(s)))
#define FMA2(acc, a, b) asm("fma.rn.f32x2 %0, %1, %2, %0;" : "+l"(acc) : "l"(a), "l"(b))
#define UNPACK2(lo, hi, s) asm("mov.b64 {%0,%1}, %2;" : "=r"(lo), "=r"(hi) : "l"(s))

// ---------------------------------------------------------------------------
// Complex SGEMM, STAGE-specialized (identical structure to the passing R4
// kernel; inner product rewritten with packed f32x2 FMAs).
//   STAGE 0:  Q = WKQ @ E          STAGE 1:  P = WPV @ E
//   STAGE 2:  S = E^H @ Q (i<=j)   STAGE 3:  out = (1/j) P @ S
// Tiling: 128x128x8, 256 threads, 8x8 complex per thread (2x2 quads of 4x4),
// accumulators packed in pairs along n.
// ---------------------------------------------------------------------------
constexpr int BM = 128, BN = 128, BK = 8;

template <int STAGE>
__global__ __launch_bounds__(256, 1)
void cgemm_kernel(const float* __restrict__ Are, const float* __restrict__ Aim,
                  const float* __restrict__ Bre, const float* __restrict__ Bim,
                  float* __restrict__ outP, int omode, long long ocap)
{
    constexpr int  LDA    = (STAGE <= 1) ? ND2 : NT;
    constexpr int  LDB    = NT;
    constexpr int  K_TOT  = (STAGE == 3) ? NT : ND2;
    constexpr bool ATRANS = (STAGE == 2);
    constexpr bool CONJA  = (STAGE == 2);

    const int bz = blockIdx.z;
    const int n0 = blockIdx.x * BN;
    const int m0 = blockIdx.y * BM;

    if (STAGE == 2 && m0 > n0) return;  // tile entirely below diagonal

    const float *are, *aim, *bre, *bim;
    if (STAGE == 0 || STAGE == 1) {
        are = Are;  aim = Aim;
        bre = Bre + (size_t)bz * ND2 * NT;
        bim = Bim + (size_t)bz * ND2 * NT;
    } else if (STAGE == 2) {
        are = Are + (size_t)bz * ND2 * NT;
        aim = Aim + (size_t)bz * ND2 * NT;
        bre = g_Q_re + (size_t)bz * ND2 * NT;
        bim = g_Q_im + (size_t)bz * ND2 * NT;
    } else {
        are = g_P_re + (size_t)bz * NDIM * NT;
        aim = g_P_im + (size_t)bz * NDIM * NT;
        bre = g_S_re + (size_t)bz * NT * NT;
        bim = g_S_im + (size_t)bz * NT * NT;
    }

    int kEnd = K_TOT;
    if (STAGE == 3) { int ke = n0 + BN; kEnd = ke < K_TOT ? ke : K_TOT; }

    __shared__ float As[2][BK][BM];
    __shared__ float Bs[2][BK][BN];

    // Packed accumulators: [mi][ni][ii][p], p = n-pair (2 cols each)
    unsigned long long accRe[2][2][4][2] = {};
    unsigned long long accIm[2][2][4][2] = {};

    const int tid = threadIdx.x;
    const int tx  = tid & 15;
    const int ty  = tid >> 4;

    for (int k0 = 0; k0 < kEnd; k0 += BK) {
        if (ATRANS) {
            const int ak = tid >> 5;
            const int am = (tid & 31) << 2;
            *(float4*)&As[0][ak][am] = *(const float4*)(are + (size_t)(k0 + ak) * LDA + (m0 + am));
            *(float4*)&As[1][ak][am] = *(const float4*)(aim + (size_t)(k0 + ak) * LDA + (m0 + am));
        } else {
            const int arow = tid >> 1;
            const int ak   = (tid & 1) << 2;
            const float4 vr = *(const float4*)(are + (size_t)(m0 + arow) * LDA + (k0 + ak));
            const float4 vi = *(const float4*)(aim + (size_t)(m0 + arow) * LDA + (k0 + ak));
            As[0][ak + 0][arow] = vr.x; As[0][ak + 1][arow] = vr.y;
            As[0][ak + 2][arow] = vr.z; As[0][ak + 3][arow] = vr.w;
            As[1][ak + 0][arow] = vi.x; As[1][ak + 1][arow] = vi.y;
            As[1][ak + 2][arow] = vi.z; As[1][ak + 3][arow] = vi.w;
        }
        {
            const int bk = tid >> 5;
            const int bn = (tid & 31) << 2;
            *(float4*)&Bs[0][bk][bn] = *(const float4*)(bre + (size_t)(k0 + bk) * LDB + (n0 + bn));
            *(float4*)&Bs[1][bk][bn] = *(const float4*)(bim + (size_t)(k0 + bk) * LDB + (n0 + bn));
        }
        __syncthreads();

        #pragma unroll
        for (int kk = 0; kk < BK; kk++) {
            float ar[2][4], ai[2][4];
            *(float4*)ar[0] = *(const float4*)&As[0][kk][(ty << 2)];
            *(float4*)ar[1] = *(const float4*)&As[0][kk][64 + (ty << 2)];
            *(float4*)ai[0] = *(const float4*)&As[1][kk][(ty << 2)];
            *(float4*)ai[1] = *(const float4*)&As[1][kk][64 + (ty << 2)];

            // B pairs as packed f32x2 (8-byte aligned LDS.64)
            unsigned long long br2[2][2], bi2[2][2];
            #pragma unroll
            for (int ni = 0; ni < 2; ni++)
              #pragma unroll
              for (int p = 0; p < 2; p++) {
                br2[ni][p] = *(const unsigned long long*)&Bs[0][kk][ni * 64 + (tx << 2) + p * 2];
                bi2[ni][p] = *(const unsigned long long*)&Bs[1][kk][ni * 64 + (tx << 2) + p * 2];
              }

            #pragma unroll
            for (int mi = 0; mi < 2; mi++)
              #pragma unroll
              for (int ii = 0; ii < 4; ii++) {
                const float xr = ar[mi][ii], xi = ai[mi][ii];
                unsigned long long xr2, xi2, nxi2;
                PACK2(xr2, xr);
                PACK2(xi2, xi);
                PACK2(nxi2, -xi);
                #pragma unroll
                for (int ni = 0; ni < 2; ni++)
                  #pragma unroll
                  for (int p = 0; p < 2; p++) {
                    if (CONJA) {
                        // conj(a)*b: re += xr*yr + xi*yi ; im += xr*yi - xi*yr
                        FMA2(accRe[mi][ni][ii][p], xr2,  br2[ni][p]);
                        FMA2(accRe[mi][ni][ii][p], xi2,  bi2[ni][p]);
                        FMA2(accIm[mi][ni][ii][p], xr2,  bi2[ni][p]);
                        FMA2(accIm[mi][ni][ii][p], nxi2, br2[ni][p]);
                    } else {
                        // a*b: re += xr*yr - xi*yi ; im += xr*yi + xi*yr
                        FMA2(accRe[mi][ni][ii][p], xr2,  br2[ni][p]);
                        FMA2(accRe[mi][ni][ii][p], nxi2, bi2[ni][p]);
                        FMA2(accIm[mi][ni][ii][p], xr2,  bi2[ni][p]);
                        FMA2(accIm[mi][ni][ii][p], xi2,  br2[ni][p]);
                    }
                  }
              }
        }
        __syncthreads();
    }

    // ---- epilogue ----
    float *cre = nullptr, *cim = nullptr;
    if (STAGE == 0) { cre = g_Q_re + (size_t)bz * ND2 * NT;  cim = g_Q_im + (size_t)bz * ND2 * NT; }
    if (STAGE == 1) { cre = g_P_re + (size_t)bz * NDIM * NT; cim = g_P_im + (size_t)bz * NDIM * NT; }
    if (STAGE == 2) { cre = g_S_re + (size_t)bz * NT * NT;   cim = g_S_im + (size_t)bz * NT * NT; }

    #pragma unroll
    for (int mi = 0; mi < 2; mi++)
      #pragma unroll
      for (int ii = 0; ii < 4; ii++) {
        const int row = m0 + mi * 64 + (ty << 2) + ii;
        #pragma unroll
        for (int ni = 0; ni < 2; ni++)
          #pragma unroll
          for (int p = 0; p < 2; p++) {
            uint32_t r0u, r1u, i0u, i1u;
            UNPACK2(r0u, r1u, accRe[mi][ni][ii][p]);
            UNPACK2(i0u, i1u, accIm[mi][ni][ii][p]);
            const float vre[2] = {__uint_as_float(r0u), __uint_as_float(r1u)};
            const float vim[2] = {__uint_as_float(i0u), __uint_as_float(i1u)};
            #pragma unroll
            for (int e = 0; e < 2; e++) {
                const int col = n0 + ni * 64 + (tx << 2) + p * 2 + e;
                float vr = vre[e], vi = vim[e];
                if (STAGE == 3) {
                    if (col >= 1 && col <= NTOUT) {
                        const float s = 1.0f / (float)col;
                        const long long o = ((long long)bz * NDIM + row) * NTOUT + (col - 1);
                        if (omode == 0) {
                            if (2 * o + 1 < ocap) { outP[2 * o] = vr * s; outP[2 * o + 1] = vi * s; }
                        } else {
                            if (o < ocap) outP[o] = vr * s;
                        }
                    }
                } else {
                    if (STAGE == 2 && row > col) { vr = 0.0f; vi = 0.0f; }  // causal
                    cre[(size_t)row * NT + col] = vr;
                    cim[(size_t)row * NT + col] = vi;
                }
            }
          }
      }
}

extern "C" void kernel_launch(void* const* d_in, const int* in_sizes, int n_in,
                              void* d_out, int out_size)
{
    const float* Eptr[2]   = {nullptr, nullptr};
    const float* WKQptr[2] = {nullptr, nullptr};
    const float* WPVptr[2] = {nullptr, nullptr};
    int ne = 0, nk = 0, np = 0;
    for (int i = 0; i < n_in; i++) {
        const float* p = (const float*)d_in[i];
        const long long s = in_sizes[i];
        if (s == SZ_E || s == 4LL * SZ_E)          { if (ne < 2) Eptr[ne++]   = p; }
        else if (s == SZ_WKQ || s == 4LL * SZ_WKQ) { if (nk < 2) WKQptr[nk++] = p; }
        else if (s == SZ_WPV || s == 4LL * SZ_WPV) { if (np < 2) WPVptr[np++] = p; }
    }
    if (ne != 2 || nk != 2 || np != 2) {
        Eptr[0]   = (const float*)d_in[0]; Eptr[1]   = (const float*)d_in[1];
        WKQptr[0] = (const float*)d_in[2]; WKQptr[1] = (const float*)d_in[3];
        WPVptr[0] = (const float*)d_in[4]; WPVptr[1] = (const float*)d_in[5];
    }
    const float* E_re   = Eptr[0];   const float* E_im   = Eptr[1];
    const float* WKQ_re = WKQptr[0]; const float* WKQ_im = WKQptr[1];
    const float* WPV_re = WPVptr[0]; const float* WPV_im = WPVptr[1];
    float* out = (float*)d_out;

    int omode; long long ocap;
    if (out_size >= OUT_CPLX)      { omode = 0; ocap = out_size; }
    else if (out_size == OUT_REAL) { omode = 1; ocap = out_size; }
    else                           { omode = 0; ocap = out_size; }

    const dim3 blk(256);
    cgemm_kernel<0><<<dim3(NT / BN, ND2 / BM, NB), blk>>>(WKQ_re, WKQ_im, E_re, E_im, nullptr, 0, 0);
    cgemm_kernel<1><<<dim3(NT / BN, NDIM / BM, NB), blk>>>(WPV_re, WPV_im, E_re, E_im, nullptr, 0, 0);
    cgemm_kernel<2><<<dim3(NT / BN, NT / BM, NB), blk>>>(E_re, E_im, nullptr, nullptr, nullptr, 0, 0);
    cgemm_kernel<3><<<dim3(NT / BN, NDIM / BM, NB), blk>>>(nullptr, nullptr, nullptr, nullptr, out, omode, ocap);
}

// round 17
// speedup vs baseline: 2.7301x; 1.2011x over previous
#include <cuda_runtime.h>
#include <cstdint>

// Problem constants
#define NB    8
#define NDIM  512
#define ND2   1024
#define NT    2048
#define NTOUT 2046   // output columns j = 1 .. T-2

#define SZ_E   (NB * ND2 * NT)
#define SZ_WKQ (ND2 * ND2)
#define SZ_WPV (NDIM * ND2)
#define OUT_CPLX (2 * NB * NDIM * NTOUT)
#define OUT_REAL (NB * NDIM * NTOUT)

// fp32 scratch (.bss zero-init). g_S lower triangle never written -> stays 0.
__device__ float g_Q_re[(size_t)NB * ND2 * NT];
__device__ float g_Q_im[(size_t)NB * ND2 * NT];
__device__ float g_P_re[(size_t)NB * NDIM * NT];
__device__ float g_P_im[(size_t)NB * NDIM * NT];
__device__ float g_S_re[(size_t)NB * NT * NT];
__device__ float g_S_im[(size_t)NB * NT * NT];

// Packed f32x2 helpers (Blackwell FFMA2 via PTX)
#define PACK2(d, s)  asm("mov.b64 %0, {%1,%1};" : "=l"(d) : "r"(__float_as_uint(s)))
#define FMA2(acc, a, b) asm("fma.rn.f32x2 %0, %1, %2, %0;" : "+l"(acc) : "l"(a), "l"(b))
#define UNPACK2(lo, hi, s) asm("mov.b64 {%0,%1}, %2;" : "=r"(lo), "=r"(hi) : "l"(s))

// ---------------------------------------------------------------------------
// Complex SGEMM with 3M (Karatsuba) multiply and FFMA2.
//   STAGE 0:  Q = WKQ @ E          STAGE 1:  P = WPV @ E
//   STAGE 2:  S = E^H @ Q (i<=j)   STAGE 3:  out = (1/j) P @ S
// Tile 128x64, BK=16, 256 threads, 8x4 complex per thread.
// Smem planes: 0=re, 1=im, 2=sum (A: re±im per stage; B: re+im).
// Accumulators: m1=Σxr·yr, m2=Σxi·yi, m3=Σxs·ys, packed in n-pairs.
//   non-conj: re=m1−m2, im=m3−m1−m2 ; conj-A(stage2): re=m1+m2, im=m3−m1+m2
// ---------------------------------------------------------------------------
constexpr int BM = 128, BN = 64, BK = 16;

template <int STAGE>
__global__ __launch_bounds__(256, 1)
void cgemm_kernel(const float* __restrict__ Are, const float* __restrict__ Aim,
                  const float* __restrict__ Bre, const float* __restrict__ Bim,
                  float* __restrict__ outP, int omode, long long ocap)
{
    constexpr int  LDA    = (STAGE <= 1) ? ND2 : NT;
    constexpr int  LDB    = NT;
    constexpr int  K_TOT  = (STAGE == 3) ? NT : ND2;
    constexpr bool ATRANS = (STAGE == 2);   // A stored [K][M]
    constexpr bool CONJA  = (STAGE == 2);   // A-sum plane uses re - im

    const int bz = blockIdx.z;
    const int n0 = blockIdx.x * BN;
    const int m0 = blockIdx.y * BM;

    if (STAGE == 2 && m0 > n0) return;  // tile entirely below diagonal

    const float *are, *aim, *bre, *bim;
    if (STAGE == 0 || STAGE == 1) {
        are = Are;  aim = Aim;
        bre = Bre + (size_t)bz * ND2 * NT;
        bim = Bim + (size_t)bz * ND2 * NT;
    } else if (STAGE == 2) {
        are = Are + (size_t)bz * ND2 * NT;
        aim = Aim + (size_t)bz * ND2 * NT;
        bre = g_Q_re + (size_t)bz * ND2 * NT;
        bim = g_Q_im + (size_t)bz * ND2 * NT;
    } else {
        are = g_P_re + (size_t)bz * NDIM * NT;
        aim = g_P_im + (size_t)bz * NDIM * NT;
        bre = g_S_re + (size_t)bz * NT * NT;
        bim = g_S_im + (size_t)bz * NT * NT;
    }

    int kEnd = K_TOT;
    if (STAGE == 3) { int ke = n0 + BN; kEnd = ke < K_TOT ? ke : K_TOT; }  // i <= j

    __shared__ float As[3][BK][BM];   // 24 KB
    __shared__ float Bs[3][BK][BN];   // 12 KB

    // Accumulators: [mi][ii][p] packed pairs; 3 sets (m1, m2, m3)
    unsigned long long a1[2][4][2] = {}, a2[2][4][2] = {}, a3[2][4][2] = {};

    const int tid = threadIdx.x;
    const int tx  = tid & 15;   // n: tx*4 .. tx*4+3 (2 pairs)
    const int ty  = tid >> 4;   // m: ty*4(+ii), +64 for mi=1

    for (int k0 = 0; k0 < kEnd; k0 += BK) {
        // ---- A tile ----
        if (ATRANS) {
            // A stored [K][M], M contiguous: k = tid>>4 (16), am = (tid&15)*8
            const int ak = tid >> 4;
            const int am = (tid & 15) << 3;
            #pragma unroll
            for (int c = 0; c < 2; c++) {
                const float4 vr = *(const float4*)(are + (size_t)(k0 + ak) * LDA + (m0 + am) + c * 4);
                const float4 vi = *(const float4*)(aim + (size_t)(k0 + ak) * LDA + (m0 + am) + c * 4);
                float4 vs;
                vs.x = CONJA ? vr.x - vi.x : vr.x + vi.x;
                vs.y = CONJA ? vr.y - vi.y : vr.y + vi.y;
                vs.z = CONJA ? vr.z - vi.z : vr.z + vi.z;
                vs.w = CONJA ? vr.w - vi.w : vr.w + vi.w;
                *(float4*)&As[0][ak][am + c * 4] = vr;
                *(float4*)&As[1][ak][am + c * 4] = vi;
                *(float4*)&As[2][ak][am + c * 4] = vs;
            }
        } else {
            // A stored [M][K]: arow = tid>>1 (128), ak = (tid&1)*8, transpose-store
            const int arow = tid >> 1;
            const int ak   = (tid & 1) << 3;
            #pragma unroll
            for (int c = 0; c < 2; c++) {
                const float4 vr = *(const float4*)(are + (size_t)(m0 + arow) * LDA + (k0 + ak) + c * 4);
                const float4 vi = *(const float4*)(aim + (size_t)(m0 + arow) * LDA + (k0 + ak) + c * 4);
                const float rr[4] = {vr.x, vr.y, vr.z, vr.w};
                const float ii_[4] = {vi.x, vi.y, vi.z, vi.w};
                #pragma unroll
                for (int j = 0; j < 4; j++) {
                    As[0][ak + c * 4 + j][arow] = rr[j];
                    As[1][ak + c * 4 + j][arow] = ii_[j];
                    As[2][ak + c * 4 + j][arow] = CONJA ? rr[j] - ii_[j] : rr[j] + ii_[j];
                }
            }
        }
        // ---- B tile ([K][N], N contiguous): k = tid>>4, bn = (tid&15)*4 ----
        {
            const int bk = tid >> 4;
            const int bn = (tid & 15) << 2;
            const float4 vr = *(const float4*)(bre + (size_t)(k0 + bk) * LDB + (n0 + bn));
            const float4 vi = *(const float4*)(bim + (size_t)(k0 + bk) * LDB + (n0 + bn));
            float4 vs;
            vs.x = vr.x + vi.x; vs.y = vr.y + vi.y; vs.z = vr.z + vi.z; vs.w = vr.w + vi.w;
            *(float4*)&Bs[0][bk][bn] = vr;
            *(float4*)&Bs[1][bk][bn] = vi;
            *(float4*)&Bs[2][bk][bn] = vs;
        }
        __syncthreads();

        #pragma unroll
        for (int kk = 0; kk < BK; kk++) {
            float ar[2][4], ai[2][4], as_[2][4];
            *(float4*)ar[0]  = *(const float4*)&As[0][kk][(ty << 2)];
            *(float4*)ar[1]  = *(const float4*)&As[0][kk][64 + (ty << 2)];
            *(float4*)ai[0]  = *(const float4*)&As[1][kk][(ty << 2)];
            *(float4*)ai[1]  = *(const float4*)&As[1][kk][64 + (ty << 2)];
            *(float4*)as_[0] = *(const float4*)&As[2][kk][(ty << 2)];
            *(float4*)as_[1] = *(const float4*)&As[2][kk][64 + (ty << 2)];

            unsigned long long br2[2], bi2[2], bs2[2];
            #pragma unroll
            for (int p = 0; p < 2; p++) {
                br2[p] = *(const unsigned long long*)&Bs[0][kk][(tx << 2) + p * 2];
                bi2[p] = *(const unsigned long long*)&Bs[1][kk][(tx << 2) + p * 2];
                bs2[p] = *(const unsigned long long*)&Bs[2][kk][(tx << 2) + p * 2];
            }

            #pragma unroll
            for (int mi = 0; mi < 2; mi++)
              #pragma unroll
              for (int ii = 0; ii < 4; ii++) {
                unsigned long long xr2, xi2, xs2;
                PACK2(xr2, ar[mi][ii]);
                PACK2(xi2, ai[mi][ii]);
                PACK2(xs2, as_[mi][ii]);
                #pragma unroll
                for (int p = 0; p < 2; p++) {
                    FMA2(a1[mi][ii][p], xr2, br2[p]);
                    FMA2(a2[mi][ii][p], xi2, bi2[p]);
                    FMA2(a3[mi][ii][p], xs2, bs2[p]);
                }
              }
        }
        __syncthreads();
    }

    // ---- epilogue ----
    float *cre = nullptr, *cim = nullptr;
    if (STAGE == 0) { cre = g_Q_re + (size_t)bz * ND2 * NT;  cim = g_Q_im + (size_t)bz * ND2 * NT; }
    if (STAGE == 1) { cre = g_P_re + (size_t)bz * NDIM * NT; cim = g_P_im + (size_t)bz * NDIM * NT; }
    if (STAGE == 2) { cre = g_S_re + (size_t)bz * NT * NT;   cim = g_S_im + (size_t)bz * NT * NT; }

    #pragma unroll
    for (int mi = 0; mi < 2; mi++)
      #pragma unroll
      for (int ii = 0; ii < 4; ii++) {
        const int row = m0 + mi * 64 + (ty << 2) + ii;
        #pragma unroll
        for (int p = 0; p < 2; p++) {
            uint32_t u1a, u1b, u2a, u2b, u3a, u3b;
            UNPACK2(u1a, u1b, a1[mi][ii][p]);
            UNPACK2(u2a, u2b, a2[mi][ii][p]);
            UNPACK2(u3a, u3b, a3[mi][ii][p]);
            const float m1[2] = {__uint_as_float(u1a), __uint_as_float(u1b)};
            const float m2[2] = {__uint_as_float(u2a), __uint_as_float(u2b)};
            const float m3[2] = {__uint_as_float(u3a), __uint_as_float(u3b)};
            #pragma unroll
            for (int e = 0; e < 2; e++) {
                const int col = n0 + (tx << 2) + p * 2 + e;
                float vr, vi;
                if (CONJA) { vr = m1[e] + m2[e]; vi = m3[e] - m1[e] + m2[e]; }
                else       { vr = m1[e] - m2[e]; vi = m3[e] - m1[e] - m2[e]; }
                if (STAGE == 3) {
                    if (col >= 1 && col <= NTOUT) {
                        const float s = 1.0f / (float)col;
                        const long long o = ((long long)bz * NDIM + row) * NTOUT + (col - 1);
                        if (omode == 0) {
                            if (2 * o + 1 < ocap) { outP[2 * o] = vr * s; outP[2 * o + 1] = vi * s; }
                        } else {
                            if (o < ocap) outP[o] = vr * s;
                        }
                    }
                } else {
                    if (STAGE == 2 && row > col) { vr = 0.0f; vi = 0.0f; }  // causal
                    cre[(size_t)row * NT + col] = vr;
                    cim[(size_t)row * NT + col] = vi;
                }
            }
        }
      }
}

extern "C" void kernel_launch(void* const* d_in, const int* in_sizes, int n_in,
                              void* d_out, int out_size)
{
    const float* Eptr[2]   = {nullptr, nullptr};
    const float* WKQptr[2] = {nullptr, nullptr};
    const float* WPVptr[2] = {nullptr, nullptr};
    int ne = 0, nk = 0, np = 0;
    for (int i = 0; i < n_in; i++) {
        const float* p = (const float*)d_in[i];
        const long long s = in_sizes[i];
        if (s == SZ_E || s == 4LL * SZ_E)          { if (ne < 2) Eptr[ne++]   = p; }
        else if (s == SZ_WKQ || s == 4LL * SZ_WKQ) { if (nk < 2) WKQptr[nk++] = p; }
        else if (s == SZ_WPV || s == 4LL * SZ_WPV) { if (np < 2) WPVptr[np++] = p; }
    }
    if (ne != 2 || nk != 2 || np != 2) {
        Eptr[0]   = (const float*)d_in[0]; Eptr[1]   = (const float*)d_in[1];
        WKQptr[0] = (const float*)d_in[2]; WKQptr[1] = (const float*)d_in[3];
        WPVptr[0] = (const float*)d_in[4]; WPVptr[1] = (const float*)d_in[5];
    }
    const float* E_re   = Eptr[0];   const float* E_im   = Eptr[1];
    const float* WKQ_re = WKQptr[0]; const float* WKQ_im = WKQptr[1];
    const float* WPV_re = WPVptr[0]; const float* WPV_im = WPVptr[1];
    float* out = (float*)d_out;

    int omode; long long ocap;
    if (out_size >= OUT_CPLX)      { omode = 0; ocap = out_size; }
    else if (out_size == OUT_REAL) { omode = 1; ocap = out_size; }
    else                           { omode = 0; ocap = out_size; }

    const dim3 blk(256);
    cgemm_kernel<0><<<dim3(NT / BN, ND2 / BM, NB), blk>>>(WKQ_re, WKQ_im, E_re, E_im, nullptr, 0, 0);
    cgemm_kernel<1><<<dim3(NT / BN, NDIM / BM, NB), blk>>>(WPV_re, WPV_im, E_re, E_im, nullptr, 0, 0);
    cgemm_kernel<2><<<dim3(NT / BN, NT / BM, NB), blk>>>(E_re, E_im, nullptr, nullptr, nullptr, 0, 0);
    cgemm_kernel<3><<<dim3(NT / BN, NDIM / BM, NB), blk>>>(nullptr, nullptr, nullptr, nullptr, out, omode, ocap);
}